// round 1
// baseline (speedup 1.0000x reference)
#include <cuda_runtime.h>
#include <math.h>

#define HIDDEN 256
#define T_HOR  24
#define FMET   16
#define B_SZ   16
#define N_SZ   1000
#define EPS_LN 1e-5f

#define TPB       128   // threads per block (each owns 2 hidden columns)
#define XT_STRIDE 26    // padded transposed-row length (24 rows -> 26, keeps 8B pair alignment)
#define RED_STR   (TPB + 4)

typedef unsigned long long u64;

__device__ __forceinline__ u64 pack2(float lo, float hi) {
    u64 r; asm("mov.b64 %0, {%1, %2};" : "=l"(r) : "f"(lo), "f"(hi)); return r;
}
__device__ __forceinline__ void unpack2(u64 v, float &lo, float &hi) {
    asm("mov.b64 {%0, %1}, %2;" : "=f"(lo), "=f"(hi) : "l"(v));
}
// packed double fp32 FMA (sm_100+): d = a*b + d  on two lanes
__device__ __forceinline__ void ffma2(u64 &d, u64 a, u64 b) {
    asm("fma.rn.f32x2 %0, %1, %2, %0;" : "+l"(d) : "l"(a), "l"(b));
}

__device__ __forceinline__ float gelu_exact(float x) {
    return 0.5f * x * (1.0f + erff(x * 0.70710678118654752440f));
}

__global__ void __launch_bounds__(TPB)
dhh_kernel(const float* __restrict__ final_h,
           const float* __restrict__ future_met,
           const float* __restrict__ step_q,
           const float* __restrict__ W_fm,
           const float* __restrict__ b_fm,
           const float* __restrict__ gamma,
           const float* __restrict__ beta,
           const float* __restrict__ W1,
           const float* __restrict__ b1,
           const float* __restrict__ W2,
           const float* __restrict__ b2,
           float* __restrict__ out)
{
    // transposed activations: xT[k][r], k = hidden col 0..255, r = horizon 0..23
    __shared__ __align__(16) float xT[HIDDEN * XT_STRIDE];   // 26624 B
    __shared__ float fm_s[T_HOR * FMET];                      // 1536 B
    __shared__ float red[T_HOR * RED_STR];                    // 12672 B

    const int tid = threadIdx.x;
    const int bn  = blockIdx.x;           // (b, n) pair
    const int b   = bn / N_SZ;
    const int n   = bn - b * N_SZ;
    const int c0  = tid * 2;              // this thread's two hidden columns

    // stage future_met[b, :, n, :]  (24 x 16)
    for (int i = tid; i < T_HOR * FMET; i += TPB) {
        int t = i >> 4, f = i & 15;
        fm_s[i] = future_met[((size_t)(b * T_HOR + t) * N_SZ + n) * FMET + f];
    }

    // per-thread column constants
    float2 wfm[FMET];
#pragma unroll
    for (int f = 0; f < FMET; f++)
        wfm[f] = *(const float2*)&W_fm[f * HIDDEN + c0];
    const float2 fh = *(const float2*)&final_h[(size_t)bn * HIDDEN + c0];
    const float2 bf = *(const float2*)&b_fm[c0];

    __syncthreads();

    // ---- Phase A: combined = final_h + step_q + (fm @ W_fm + b_fm), write transposed ----
#pragma unroll 4
    for (int t = 0; t < T_HOR; t++) {
        float2 q = *(const float2*)&step_q[t * HIDDEN + c0];
        float sx = fh.x + q.x + bf.x;
        float sy = fh.y + q.y + bf.y;
#pragma unroll
        for (int f = 0; f < FMET; f++) {
            float m = fm_s[t * FMET + f];
            sx = fmaf(m, wfm[f].x, sx);
            sy = fmaf(m, wfm[f].y, sy);
        }
        xT[c0 * XT_STRIDE + t]       = sx;
        xT[(c0 + 1) * XT_STRIDE + t] = sy;
    }
    __syncthreads();

    // ---- Phase B: LayerNorm across hidden dim, one warp handles 6 rows ----
    const int wid = tid >> 5, lane = tid & 31;
    for (int r = wid * 6; r < wid * 6 + 6; r++) {
        float s = 0.f, s2 = 0.f;
        float v[8];
#pragma unroll
        for (int i = 0; i < 8; i++) {
            v[i] = xT[(lane + 32 * i) * XT_STRIDE + r];
            s += v[i];
            s2 = fmaf(v[i], v[i], s2);
        }
#pragma unroll
        for (int o = 16; o; o >>= 1) {
            s  += __shfl_xor_sync(0xffffffffu, s, o);
            s2 += __shfl_xor_sync(0xffffffffu, s2, o);
        }
        const float mu   = s * (1.0f / HIDDEN);
        const float var  = s2 * (1.0f / HIDDEN) - mu * mu;
        const float rstd = rsqrtf(var + EPS_LN);
#pragma unroll
        for (int i = 0; i < 8; i++) {
            int k = lane + 32 * i;
            xT[k * XT_STRIDE + r] = (v[i] - mu) * rstd * gamma[k] + beta[k];
        }
    }
    __syncthreads();

    // ---- Phase C: x(24x256) @ W1(256x256) with packed f32x2 FMAs ----
    u64 acc0[12], acc1[12];
#pragma unroll
    for (int p = 0; p < 12; p++) { acc0[p] = 0ull; acc1[p] = 0ull; }

    const float* w1p = &W1[c0];
#pragma unroll 4
    for (int k = 0; k < HIDDEN; k++) {
        float2 w = *(const float2*)(w1p + (size_t)k * HIDDEN);   // coalesced 256-float row
        u64 w20 = pack2(w.x, w.x);
        u64 w21 = pack2(w.y, w.y);
        const u64* xr = (const u64*)&xT[k * XT_STRIDE];          // 12 row-pairs, broadcast
#pragma unroll
        for (int p = 0; p < 12; p++) {
            u64 xp = xr[p];
            ffma2(acc0[p], xp, w20);
            ffma2(acc1[p], xp, w21);
        }
    }

    // ---- GELU + W2 projection (partial per thread) ----
    const float wa = W2[c0], wb = W2[c0 + 1];
    const float ba = b1[c0], bb = b1[c0 + 1];
#pragma unroll
    for (int p = 0; p < 12; p++) {
        float a0, a1, d0, d1;
        unpack2(acc0[p], a0, a1);   // col c0, rows 2p / 2p+1
        unpack2(acc1[p], d0, d1);   // col c0+1
        a0 += ba; a1 += ba; d0 += bb; d1 += bb;
        float pr0 = gelu_exact(a0) * wa + gelu_exact(d0) * wb;
        float pr1 = gelu_exact(a1) * wa + gelu_exact(d1) * wb;
        red[(2 * p)     * RED_STR + tid] = pr0;
        red[(2 * p + 1) * RED_STR + tid] = pr1;
    }
    __syncthreads();

    // ---- cross-thread reduction + output (B,T,N,1) ----
    if (tid < T_HOR) {
        const float* rr = &red[tid * RED_STR];
        float s = 0.f;
#pragma unroll 8
        for (int j = 0; j < TPB; j++) s += rr[j];
        out[(size_t)(b * T_HOR + tid) * N_SZ + n] = s + b2[0];
    }
}

extern "C" void kernel_launch(void* const* d_in, const int* in_sizes, int n_in,
                              void* d_out, int out_size) {
    const float* final_h    = (const float*)d_in[0];
    const float* future_met = (const float*)d_in[1];
    const float* step_q     = (const float*)d_in[2];
    const float* W_fm       = (const float*)d_in[3];
    const float* b_fm       = (const float*)d_in[4];
    const float* gamma      = (const float*)d_in[5];
    const float* beta       = (const float*)d_in[6];
    const float* W1         = (const float*)d_in[7];
    const float* b1         = (const float*)d_in[8];
    const float* W2         = (const float*)d_in[9];
    const float* b2         = (const float*)d_in[10];
    float* out = (float*)d_out;

    dhh_kernel<<<B_SZ * N_SZ, TPB>>>(final_h, future_met, step_q, W_fm, b_fm,
                                     gamma, beta, W1, b1, W2, b2, out);
}

// round 3
// speedup vs baseline: 1.3630x; 1.3630x over previous
#include <cuda_runtime.h>
#include <cuda_bf16.h>
#include <math.h>
#include <stdint.h>

#define HIDDEN 256
#define T_HOR  24
#define FMET   16
#define B_SZ   16
#define N_SZ   1000
#define GRP    5
#define TPB    256
#define NCTA   (B_SZ * (N_SZ / GRP))   // 3200
#define EPS_LN 1e-5f

// ---- smem layout (bytes) ----
#define OFF_AHI   0         // A hi fragments, 64KB
#define OFF_ALO   65536     // A lo fragments, 64KB
#define OFF_B     131072    // B double buffer, 2 x 32KB
// phase-A staging window overlaps B buffers (dead before first cp.async)
#define OFF_QB    131072    // 24*258*4 = 24768
#define OFF_WFM   155840    // 16384
#define OFF_FH    172224    // 5120
#define OFF_FM    177344    // 7680
#define OFF_GAM   185024    // 1024
// persistent smalls
#define OFF_STS   196608    // 1024
#define OFF_STS2  197632    // 1024
#define OFF_RED   198656    // 4096 (128 rows x 8 slots)
#define OFF_CS    202752    // 1024
#define OFF_GS    203776    // 1024
#define OFF_W2S   204800    // 1024
#define SMEM_TOTAL 205824

// W1 pre-packed in mma-fragment layout:
// [chunk 8][split 2][kstep 2][ntile 32][lane 32][reg 2]  (u32 each)
__device__ __align__(16) uint32_t g_Bpk[8 * 8192];
__device__ float g_C[HIDDEN];
__device__ float g_G[HIDDEN];
__device__ float g_W2[HIDDEN];

__global__ void prep_w1(const float* __restrict__ W1) {
    const int k0 = blockIdx.x * 2;          // even k of the pair
    const int n  = threadIdx.x;
    float v0 = W1[k0 * 256 + n];
    float v1 = W1[(k0 + 1) * 256 + n];
    __nv_bfloat16 h0 = __float2bfloat16(v0);
    __nv_bfloat16 h1 = __float2bfloat16(v1);
    __nv_bfloat16 l0 = __float2bfloat16(v0 - __bfloat162float(h0));
    __nv_bfloat16 l1 = __float2bfloat16(v1 - __bfloat162float(h1));
    const int chunk = k0 >> 5;
    const int kstep = (k0 >> 4) & 1;
    const int kk    = k0 & 15;
    const int ntile = n >> 3;
    const int lane  = ((n & 7) << 2) | ((kk & 7) >> 1);
    const int reg   = (kk >> 3) & 1;
    const int base  = (chunk * 2) * 4096 + kstep * 2048 + ntile * 64 + lane * 2 + reg;
    __nv_bfloat162 hp; hp.x = h0; hp.y = h1;
    __nv_bfloat162 lp; lp.x = l0; lp.y = l1;
    g_Bpk[base]        = *(uint32_t*)&hp;           // split 0 (hi)
    g_Bpk[base + 4096] = *(uint32_t*)&lp;           // split 1 (lo)
}

__global__ void prep_cg(const float* __restrict__ W1, const float* __restrict__ gamma,
                        const float* __restrict__ beta, const float* __restrict__ b1,
                        const float* __restrict__ W2) {
    int j = threadIdx.x;
    float P = 0.f, G = 0.f;
    for (int c = 0; c < 256; c++) {
        float w = W1[c * 256 + j];
        P = fmaf(beta[c], w, P);
        G = fmaf(gamma[c], w, G);
    }
    g_C[j]  = P + b1[j];
    g_G[j]  = G;
    g_W2[j] = W2[j];
}

__device__ __forceinline__ uint32_t smem_u32(const void* p) {
    uint32_t a;
    asm("{ .reg .u64 t; cvta.to.shared.u64 t, %1; cvt.u32.u64 %0, t; }" : "=r"(a) : "l"(p));
    return a;
}
__device__ __forceinline__ uint64_t to_global(const void* p) {
    uint64_t a; asm("cvta.to.global.u64 %0, %1;" : "=l"(a) : "l"(p)); return a;
}
__device__ __forceinline__ void cp_async16(uint32_t s, uint64_t g) {
    asm volatile("cp.async.cg.shared.global [%0], [%1], 16;" :: "r"(s), "l"(g) : "memory");
}
#define CP_COMMIT() asm volatile("cp.async.commit_group;" ::: "memory")
#define CP_WAIT1()  asm volatile("cp.async.wait_group 1;" ::: "memory")
#define CP_WAIT0()  asm volatile("cp.async.wait_group 0;" ::: "memory")

#define LDS128(r, addr) \
    asm volatile("ld.shared.v4.b32 {%0,%1,%2,%3}, [%4];" \
        : "=r"((r)[0]), "=r"((r)[1]), "=r"((r)[2]), "=r"((r)[3]) : "r"(addr))
#define LDS64(r, addr) \
    asm volatile("ld.shared.v2.b32 {%0,%1}, [%2];" \
        : "=r"((r)[0]), "=r"((r)[1]) : "r"(addr))

#define MMA(d, a, b) \
    asm volatile("mma.sync.aligned.m16n8k16.row.col.f32.bf16.bf16.f32 " \
        "{%0,%1,%2,%3}, {%4,%5,%6,%7}, {%8,%9}, {%0,%1,%2,%3};" \
        : "+f"((d)[0]), "+f"((d)[1]), "+f"((d)[2]), "+f"((d)[3]) \
        : "r"((a)[0]), "r"((a)[1]), "r"((a)[2]), "r"((a)[3]), \
          "r"((b)[0]), "r"((b)[1]))

__device__ __forceinline__ float gelu_exact(float x) {
    return 0.5f * x * (1.0f + erff(x * 0.70710678118654752440f));
}

__global__ void __launch_bounds__(TPB)
dhh_main(const float* __restrict__ final_h,
         const float* __restrict__ future_met,
         const float* __restrict__ step_q,
         const float* __restrict__ W_fm,
         const float* __restrict__ b_fm,
         const float* __restrict__ gamma,
         const float* __restrict__ b2,
         float* __restrict__ out)
{
    extern __shared__ __align__(1024) char smem[];
    float* smf = (float*)smem;
    const uint32_t sbase = smem_u32(smem);
    const int tid  = threadIdx.x;
    const int w    = tid >> 5;
    const int lane = tid & 31;

    const int b  = blockIdx.x / (N_SZ / GRP);
    const int n0 = (blockIdx.x % (N_SZ / GRP)) * GRP;

    // ---- stage phase-A inputs + persistent constants ----
    for (int i = tid; i < T_HOR * 256; i += TPB) {
        int t = i >> 8, c = i & 255;
        smf[OFF_QB / 4 + t * 258 + c] = step_q[i] + b_fm[c];
    }
    for (int i = tid; i < FMET * 256; i += TPB)
        smf[OFF_WFM / 4 + i] = W_fm[i];
    for (int i = tid; i < GRP * 256; i += TPB)
        smf[OFF_FH / 4 + i] = final_h[((size_t)b * N_SZ + n0) * 256 + i];
    for (int i = tid; i < GRP * T_HOR * FMET; i += TPB) {
        int ln = i / (T_HOR * FMET), r = i % (T_HOR * FMET);
        int t = r >> 4, f = r & 15;
        smf[OFF_FM / 4 + (ln * T_HOR + t) * FMET + f] =
            future_met[((size_t)(b * T_HOR + t) * N_SZ + (n0 + ln)) * FMET + f];
    }
    if (tid < 256) {
        smf[OFF_GAM / 4 + tid] = gamma[tid];
        smf[OFF_CS  / 4 + tid] = g_C[tid];
        smf[OFF_GS  / 4 + tid] = g_G[tid];
        smf[OFF_W2S / 4 + tid] = g_W2[tid];
    }
    __syncthreads();

    // ---- phase A: combined -> gamma-scaled bf16 hi/lo written in fragment layout ----
    {
        const int m = tid & 127, half = tid >> 7;
        int ln = m / 24; if (ln > 4) ln = 4;
        const int t = m % 24;
        float fmv[FMET];
#pragma unroll
        for (int f = 0; f < FMET; f++)
            fmv[f] = smf[OFF_FM / 4 + (ln * T_HOR + t) * FMET + f];

        float s = 0.f, s2 = 0.f;
        const int cb = half * 128;
        const uint32_t mbase = (uint32_t)(m >> 4) * 16;
        const uint32_t lane_m = (uint32_t)(m & 7) << 2;
        const uint32_t reg_m  = ((m & 15) >= 8) ? 1u : 0u;
#pragma unroll 4
        for (int i = 0; i < 64; i++) {
            const int c = cb + 2 * i;
            float2 qb = *(const float2*)&smf[OFF_QB / 4 + t * 258 + c];
            float2 fh = *(const float2*)&smf[OFF_FH / 4 + ln * 256 + c];
            float v0 = qb.x + fh.x, v1 = qb.y + fh.y;
#pragma unroll
            for (int f = 0; f < FMET; f++) {
                float2 wf = *(const float2*)&smf[OFF_WFM / 4 + f * 256 + c];
                v0 = fmaf(fmv[f], wf.x, v0);
                v1 = fmaf(fmv[f], wf.y, v1);
            }
            s += v0 + v1;
            s2 = fmaf(v0, v0, s2);
            s2 = fmaf(v1, v1, s2);
            float2 g2 = *(const float2*)&smf[OFF_GAM / 4 + c];
            float a0 = v0 * g2.x, a1 = v1 * g2.y;
            __nv_bfloat16 h0 = __float2bfloat16(a0);
            __nv_bfloat16 h1 = __float2bfloat16(a1);
            __nv_bfloat16 l0 = __float2bfloat16(a0 - __bfloat162float(h0));
            __nv_bfloat16 l1 = __float2bfloat16(a1 - __bfloat162float(h1));
            __nv_bfloat162 hp; hp.x = h0; hp.y = h1;
            __nv_bfloat162 lp; lp.x = l0; lp.y = l1;

            const uint32_t kk   = (uint32_t)(c & 15);
            const uint32_t lnA  = lane_m | ((kk & 7) >> 1);
            const uint32_t reg  = ((kk & 8) ? 2u : 0u) | reg_m;
            uint32_t off = ((mbase + (uint32_t)(c >> 4)) << 9) + (lnA << 4) + (reg << 2);
            off ^= (off >> 2) & 0x60;                       // anti-conflict swizzle
            *(uint32_t*)(smem + OFF_AHI + off) = *(uint32_t*)&hp;
            *(uint32_t*)(smem + OFF_ALO + off) = *(uint32_t*)&lp;
        }
        smf[OFF_STS  / 4 + m * 2 + half] = s;
        smf[OFF_STS2 / 4 + m * 2 + half] = s2;
    }
    __syncthreads();

    // ---- GEMM: 8 k32-chunks, cp.async double-buffered B, 3 split products ----
    const int wm = w & 3, wn = w >> 2;
    float acc0[16][4], acc1[16][4];
#pragma unroll
    for (int nt = 0; nt < 16; nt++)
#pragma unroll
        for (int e = 0; e < 4; e++) { acc0[nt][e] = 0.f; acc1[nt][e] = 0.f; }

    const uint32_t laneOff = ((uint32_t)lane << 4) ^ (((uint32_t)lane & 0x18) << 2);
    const uint64_t gB = to_global(g_Bpk);

    // prefetch chunk 0
    {
        uint32_t d = sbase + OFF_B + tid * 16;
        uint64_t s = gB + tid * 16;
#pragma unroll
        for (int i = 0; i < 8; i++) cp_async16(d + i * 4096, s + i * 4096);
        CP_COMMIT();
    }

    for (int c = 0; c < 8; c++) {
        if (c < 7) {
            uint32_t d = sbase + OFF_B + ((c + 1) & 1) * 32768 + tid * 16;
            uint64_t s = gB + (size_t)(c + 1) * 32768 + tid * 16;
#pragma unroll
            for (int i = 0; i < 8; i++) cp_async16(d + i * 4096, s + i * 4096);
            CP_COMMIT();
            CP_WAIT1();
        } else {
            CP_WAIT0();
        }
        __syncthreads();

        const uint32_t bufB = sbase + OFF_B + (uint32_t)(c & 1) * 32768;
#pragma unroll
        for (int kl = 0; kl < 2; kl++) {
            const uint32_t ks = (uint32_t)(c * 2 + kl);
            uint32_t ah0[4], ah1[4], al0[4], al1[4];
            const uint32_t aRow0 = (((uint32_t)(wm * 2 + 0) * 16 + ks) << 9) + laneOff;
            const uint32_t aRow1 = (((uint32_t)(wm * 2 + 1) * 16 + ks) << 9) + laneOff;
            LDS128(ah0, sbase + OFF_AHI + aRow0);
            LDS128(ah1, sbase + OFF_AHI + aRow1);
            LDS128(al0, sbase + OFF_ALO + aRow0);
            LDS128(al1, sbase + OFF_ALO + aRow1);

            const uint32_t bHi = bufB + (uint32_t)kl * 8192 + (uint32_t)(wn * 16) * 256 + (uint32_t)lane * 8;
            const uint32_t bLo = bHi + 16384;

            uint32_t bh[16][2];
#pragma unroll
            for (int nt = 0; nt < 16; nt++) LDS64(bh[nt], bHi + nt * 256);
#pragma unroll
            for (int nt = 0; nt < 16; nt++) {
                MMA(acc0[nt], ah0, bh[nt]);
                MMA(acc1[nt], ah1, bh[nt]);
                MMA(acc0[nt], al0, bh[nt]);
                MMA(acc1[nt], al1, bh[nt]);
            }
#pragma unroll
            for (int nt = 0; nt < 16; nt++) {
                uint32_t bl[2];
                LDS64(bl, bLo + nt * 256);
                MMA(acc0[nt], ah0, bl);
                MMA(acc1[nt], ah1, bl);
            }
        }
        __syncthreads();
    }

    // ---- epilogue: LN fold + exact GELU + W2 dot, reduce across threads ----
    {
        const int g = lane >> 2;
        float rstd[4], mr[4];
#pragma unroll
        for (int q = 0; q < 4; q++) {
            const int row = wm * 32 + q * 8 + g;
            const float ssum = smf[OFF_STS / 4 + row * 2] + smf[OFF_STS / 4 + row * 2 + 1];
            const float q2   = smf[OFF_STS2 / 4 + row * 2] + smf[OFF_STS2 / 4 + row * 2 + 1];
            const float mu   = ssum * (1.0f / HIDDEN);
            const float var  = q2 * (1.0f / HIDDEN) - mu * mu;
            rstd[q] = rsqrtf(var + EPS_LN);
            mr[q]   = mu * rstd[q];
        }
        float part[4] = {0.f, 0.f, 0.f, 0.f};
#pragma unroll
        for (int nt = 0; nt < 16; nt++) {
#pragma unroll
            for (int e = 0; e < 2; e++) {
                const int j = (wn * 16 + nt) * 8 + (lane & 3) * 2 + e;
                const float csj = smf[OFF_CS / 4 + j];
                const float gsj = smf[OFF_GS / 4 + j];
                const float w2j = smf[OFF_W2S / 4 + j];
#pragma unroll
                for (int q = 0; q < 4; q++) {
                    const float S = (q < 2) ? acc0[nt][(q & 1) * 2 + e]
                                            : acc1[nt][(q & 1) * 2 + e];
                    const float o = fmaf(rstd[q], S, csj) - mr[q] * gsj;
                    part[q] = fmaf(gelu_exact(o), w2j, part[q]);
                }
            }
        }
        const int slot = ((lane & 3) << 1) | wn;
#pragma unroll
        for (int q = 0; q < 4; q++) {
            const int row = wm * 32 + q * 8 + g;
            smf[OFF_RED / 4 + row * 8 + slot] = part[q];
        }
    }
    __syncthreads();

    if (tid < GRP * T_HOR) {
        const int ln = tid / T_HOR, t = tid % T_HOR;
        const float* rr = &smf[OFF_RED / 4 + tid * 8];
        float s = rr[0] + rr[1] + rr[2] + rr[3] + rr[4] + rr[5] + rr[6] + rr[7];
        out[(size_t)(b * T_HOR + t) * N_SZ + (n0 + ln)] = s + b2[0];
    }
}

extern "C" void kernel_launch(void* const* d_in, const int* in_sizes, int n_in,
                              void* d_out, int out_size) {
    const float* final_h    = (const float*)d_in[0];
    const float* future_met = (const float*)d_in[1];
    const float* step_q     = (const float*)d_in[2];
    const float* W_fm       = (const float*)d_in[3];
    const float* b_fm       = (const float*)d_in[4];
    const float* gamma      = (const float*)d_in[5];
    const float* beta       = (const float*)d_in[6];
    const float* W1         = (const float*)d_in[7];
    const float* b1         = (const float*)d_in[8];
    const float* W2         = (const float*)d_in[9];
    const float* b2         = (const float*)d_in[10];
    float* out = (float*)d_out;

    prep_w1<<<128, 256>>>(W1);
    prep_cg<<<1, 256>>>(W1, gamma, beta, b1, W2);

    cudaFuncSetAttribute(dhh_main, cudaFuncAttributeMaxDynamicSharedMemorySize, SMEM_TOTAL);
    dhh_main<<<NCTA, TPB, SMEM_TOTAL>>>(final_h, future_met, step_q, W_fm, b_fm,
                                        gamma, b2, out);
}